// round 2
// baseline (speedup 1.0000x reference)
#include <cuda_runtime.h>
#include <cuda_bf16.h>
#include <cstdint>

// ---------------- problem constants ----------------
#define NN 50000
#define EE 800000
#define DD 128
#define NWORDS 200000   // NN*DD/32

// ---------------- device scratch (no allocs allowed) ----------------
__device__ float g_H  [(size_t)NN * DD];
__device__ float g_AGG[(size_t)NN * DD];
__device__ float g_B1 [(size_t)NN * DD];
__device__ float g_B2 [(size_t)NN * DD];
__device__ int   g_cnt[NN];
__device__ int   g_cursor[NN];
__device__ int   g_rowstart[NN + 1];
__device__ float g_inv[NN];
__device__ int   g_col[EE];
__device__ float g_w[EE];
__device__ unsigned g_mask[3 * NWORDS];
__device__ int   g_is64;

// ---------------- threefry2x32 (matches JAX) ----------------
__host__ __device__ inline void tf2x32(unsigned k0, unsigned k1,
                                       unsigned x0, unsigned x1,
                                       unsigned& o0, unsigned& o1) {
    unsigned ks0 = k0, ks1 = k1, ks2 = k0 ^ k1 ^ 0x1BD11BDAu;
    x0 += ks0; x1 += ks1;
#define TFR(r) { x0 += x1; x1 = (x1 << r) | (x1 >> (32 - r)); x1 ^= x0; }
    TFR(13) TFR(15) TFR(26) TFR(6)  x0 += ks1; x1 += ks2 + 1u;
    TFR(17) TFR(29) TFR(16) TFR(24) x0 += ks2; x1 += ks0 + 2u;
    TFR(13) TFR(15) TFR(26) TFR(6)  x0 += ks0; x1 += ks1 + 3u;
    TFR(17) TFR(29) TFR(16) TFR(24) x0 += ks1; x1 += ks2 + 4u;
    TFR(13) TFR(15) TFR(26) TFR(6)  x0 += ks2; x1 += ks0 + 5u;
#undef TFR
    o0 = x0; o1 = x1;
}

// JAX threefry_partitionable=True semantics:
//   32-bit draw for flat element i under key (k0,k1):
//       (o0, o1) = threefry(k0, k1, hi=0, lo=i);  bits = o0 ^ o1      <-- FIXED
//   bernoulli(p=0.5) keep  <=>  top bit of bits == 0
__global__ void make_mask_kernel(unsigned k0, unsigned k1, unsigned* mask) {
    unsigned w = blockIdx.x * blockDim.x + threadIdx.x;
    if (w >= NWORDS) return;
    unsigned bits = 0;
#pragma unroll 8
    for (int j = 0; j < 32; j++) {
        unsigned o0, o1;
        tf2x32(k0, k1, 0u, w * 32u + (unsigned)j, o0, o1);
        unsigned draw = o0 ^ o1;            // partitionable 32-bit combine
        bits |= ((~draw) >> 31) << j;       // keep-bit (bit31==0 -> keep)
    }
    mask[w] = bits;
}

// ---------------- edge index dtype handling ----------------
__global__ void detect_kernel(const unsigned* ei) {
    if (threadIdx.x == 0 && blockIdx.x == 0) {
        int is64 = 1;
        for (int i = 0; i < 64; i++)
            if (ei[2 * i + 1] != 0u) { is64 = 0; break; }
        g_is64 = is64;
    }
}

__device__ __forceinline__ int get_edge(const void* ei, long long i) {
    if (g_is64) return (int)((const long long*)ei)[i];
    return ((const int*)ei)[i];
}

// ---------------- CSR build ----------------
__global__ void zero_kernel() {
    int i = blockIdx.x * blockDim.x + threadIdx.x;
    if (i < NN) { g_cnt[i] = 0; g_cursor[i] = 0; }
}

__global__ void count_kernel(const void* ei) {
    int e = blockIdx.x * blockDim.x + threadIdx.x;
    if (e >= EE) return;
    int r = get_edge(ei, e);
    atomicAdd(&g_cnt[r], 1);
}

__global__ void scan_kernel() {
    __shared__ int sh[1024];
    __shared__ int carry;
    int t = threadIdx.x;
    if (t == 0) carry = 0;
    __syncthreads();
    for (int base = 0; base < NN; base += 1024) {
        int v = (base + t < NN) ? g_cnt[base + t] : 0;
        sh[t] = v;
        __syncthreads();
#pragma unroll
        for (int off = 1; off < 1024; off <<= 1) {
            int add = (t >= off) ? sh[t - off] : 0;
            __syncthreads();
            sh[t] += add;
            __syncthreads();
        }
        if (base + t < NN) {
            g_rowstart[base + t] = carry + sh[t] - v;
            g_inv[base + t] = 1.0f / fmaxf((float)v, 1.0f);
        }
        int tot = sh[1023];
        __syncthreads();
        if (t == 0) carry += tot;
        __syncthreads();
    }
    if (t == 0) g_rowstart[NN] = carry;
}

__global__ void fill_kernel(const void* ei, const float* __restrict__ ew) {
    int e = blockIdx.x * blockDim.x + threadIdx.x;
    if (e >= EE) return;
    int r = get_edge(ei, e);
    int c = get_edge(ei, (long long)EE + e);
    int pos = g_rowstart[r] + atomicAdd(&g_cursor[r], 1);
    g_col[pos] = c;
    g_w[pos]   = ew[e];
}

// ---------------- gather aggregation (mean of ew * H[col]) ----------------
// one warp per node; lane l owns feature dims [4l, 4l+4)
__global__ __launch_bounds__(256) void gather_kernel(const float* __restrict__ H,
                                                     float* __restrict__ AGG) {
    int gw = (blockIdx.x * blockDim.x + threadIdx.x) >> 5;
    int lane = threadIdx.x & 31;
    if (gw >= NN) return;
    int s = g_rowstart[gw], e = g_rowstart[gw + 1];
    float4 acc = make_float4(0.f, 0.f, 0.f, 0.f);
    for (int i = s; i < e; i++) {
        int c = g_col[i];
        float ww = g_w[i];
        float4 h4 = __ldg(reinterpret_cast<const float4*>(H + (size_t)c * DD) + lane);
        acc.x += ww * h4.x; acc.y += ww * h4.y;
        acc.z += ww * h4.z; acc.w += ww * h4.w;
    }
    float sc = g_inv[gw];
    acc.x *= sc; acc.y *= sc; acc.z *= sc; acc.w *= sc;
    reinterpret_cast<float4*>(AGG + (size_t)gw * DD)[lane] = acc;
}

// ---------------- fused SGEMM: C = [A1 | A2] @ W + bias, (relu, dropout) ----------------
// BM=128, BN=128, BK=8, 256 threads, 8x8 micro-tile
template<int KTOT, bool HASA2, bool RELU, bool DROP>
__global__ __launch_bounds__(256, 2)
void gemm_kernel(const float* __restrict__ A1, const float* __restrict__ A2,
                 const float* __restrict__ W,  const float* __restrict__ bias,
                 float* __restrict__ C, int nrows, const unsigned* __restrict__ mask) {
    __shared__ float As[8][128];
    __shared__ float Bs[8][128];
    int tid = threadIdx.x;
    int ty = tid >> 4;          // 0..15
    int tx = tid & 15;          // 0..15
    int row0 = blockIdx.x * 128;

    float acc[8][8];
#pragma unroll
    for (int i = 0; i < 8; i++)
#pragma unroll
        for (int j = 0; j < 8; j++) acc[i][j] = 0.f;

    int ar  = tid >> 1;          // 0..127
    int ac4 = (tid & 1) * 4;     // 0 or 4
    int br  = tid >> 5;          // 0..7
    int bc  = (tid & 31) * 4;    // 0..124

    const int NKT = KTOT / 8;
    for (int kt = 0; kt < NKT; kt++) {
        int kbase = kt * 8;
        const float* Asrc; int kcol;
        if (HASA2 && kbase >= 128) { Asrc = A2; kcol = kbase - 128; }
        else                       { Asrc = A1; kcol = kbase; }
        float4 av = make_float4(0.f, 0.f, 0.f, 0.f);
        int gr = row0 + ar;
        if (gr < nrows)
            av = *reinterpret_cast<const float4*>(Asrc + (size_t)gr * 128 + kcol + ac4);
        float4 bv = *reinterpret_cast<const float4*>(W + (size_t)(kbase + br) * 128 + bc);
        __syncthreads();
        As[ac4 + 0][ar] = av.x; As[ac4 + 1][ar] = av.y;
        As[ac4 + 2][ar] = av.z; As[ac4 + 3][ar] = av.w;
        *reinterpret_cast<float4*>(&Bs[br][bc]) = bv;
        __syncthreads();
#pragma unroll
        for (int kk = 0; kk < 8; kk++) {
            float a0[8], b0[8];
#pragma unroll
            for (int i = 0; i < 8; i++) a0[i] = As[kk][ty * 8 + i];
#pragma unroll
            for (int j = 0; j < 8; j++) b0[j] = Bs[kk][tx * 8 + j];
#pragma unroll
            for (int i = 0; i < 8; i++)
#pragma unroll
                for (int j = 0; j < 8; j++)
                    acc[i][j] += a0[i] * b0[j];
        }
    }

    float bvreg[8];
#pragma unroll
    for (int j = 0; j < 8; j++) bvreg[j] = __ldg(&bias[tx * 8 + j]);

#pragma unroll
    for (int i = 0; i < 8; i++) {
        int r = row0 + ty * 8 + i;
        if (r < nrows) {
            unsigned m = 0xffffffffu;
            if (DROP) m = mask[(unsigned)r * 4u + (unsigned)(tx >> 2)];
            float out[8];
#pragma unroll
            for (int j = 0; j < 8; j++) {
                float v = acc[i][j] + bvreg[j];
                if (RELU) v = fmaxf(v, 0.f);
                if (DROP) {
                    int bit = (tx & 3) * 8 + j;
                    v = ((m >> bit) & 1u) ? v * 2.f : 0.f;
                }
                out[j] = v;
            }
            *reinterpret_cast<float4*>(C + (size_t)r * 128 + tx * 8) =
                make_float4(out[0], out[1], out[2], out[3]);
            *reinterpret_cast<float4*>(C + (size_t)r * 128 + tx * 8 + 4) =
                make_float4(out[4], out[5], out[6], out[7]);
        }
    }
}

// ---------------- final tiny GEMM: Y = T @ W2(128x10) + b2 ----------------
__global__ __launch_bounds__(256) void mlp_out_kernel(const float* __restrict__ T,
                                                      const float* __restrict__ W2,
                                                      const float* __restrict__ b2,
                                                      float* __restrict__ Y) {
    __shared__ float w2s[1280];
    __shared__ float b2s[10];
    int tid = threadIdx.x;
    for (int i = tid; i < 1280; i += blockDim.x) w2s[i] = W2[i];
    if (tid < 10) b2s[tid] = b2[tid];
    __syncthreads();
    int gw = (blockIdx.x * blockDim.x + tid) >> 5;
    int lane = tid & 31;
    if (gw >= NN) return;
    float4 t4 = *reinterpret_cast<const float4*>(T + (size_t)gw * 128 + lane * 4);
    float a[10];
#pragma unroll
    for (int c = 0; c < 10; c++) {
        a[c] = t4.x * w2s[(lane * 4 + 0) * 10 + c]
             + t4.y * w2s[(lane * 4 + 1) * 10 + c]
             + t4.z * w2s[(lane * 4 + 2) * 10 + c]
             + t4.w * w2s[(lane * 4 + 3) * 10 + c];
    }
#pragma unroll
    for (int c = 0; c < 10; c++) {
        float v = a[c];
        v += __shfl_xor_sync(0xffffffffu, v, 16);
        v += __shfl_xor_sync(0xffffffffu, v, 8);
        v += __shfl_xor_sync(0xffffffffu, v, 4);
        v += __shfl_xor_sync(0xffffffffu, v, 2);
        v += __shfl_xor_sync(0xffffffffu, v, 1);
        if (lane == 0) Y[(size_t)gw * 10 + c] = v + b2s[c];
    }
}

// ---------------- host launch ----------------
extern "C" void kernel_launch(void* const* d_in, const int* in_sizes, int n_in,
                              void* d_out, int out_size) {
    const float* x       = (const float*)d_in[0];
    const void*  ei      = d_in[1];
    const float* ew      = (const float*)d_in[2];
    const float* Wlin_in = (const float*)d_in[3];
    const float* blin_in = (const float*)d_in[4];
    const float* Wagg_in = (const float*)d_in[5];
    const float* bagg_in = (const float*)d_in[6];
    const float* Wlin_h  = (const float*)d_in[7];
    const float* blin_h  = (const float*)d_in[8];
    const float* Wagg_h  = (const float*)d_in[9];
    const float* bagg_h  = (const float*)d_in[10];
    const float* Wm1     = (const float*)d_in[11];
    const float* bm1     = (const float*)d_in[12];
    const float* Wm2     = (const float*)d_in[13];
    const float* bm2     = (const float*)d_in[14];

    float* out_h = (float*)d_out;
    float* out_y = out_h + (size_t)NN * DD;

    void *pH, *pAGG, *pB1, *pB2, *pMask;
    cudaGetSymbolAddress(&pH, g_H);
    cudaGetSymbolAddress(&pAGG, g_AGG);
    cudaGetSymbolAddress(&pB1, g_B1);
    cudaGetSymbolAddress(&pB2, g_B2);
    cudaGetSymbolAddress(&pMask, g_mask);
    float* H   = (float*)pH;
    float* AGG = (float*)pAGG;
    float* B1  = (float*)pB1;
    float* B2  = (float*)pB2;
    unsigned* mask0 = (unsigned*)pMask;
    unsigned* mask1 = mask0 + NWORDS;
    unsigned* mask2 = mask0 + 2 * NWORDS;

    // dropout keys: dk_i = split(key(42), 3)[i]
    // partitionable split: dk_i = both lanes of threefry((0,42), hi=0, lo=i)
    unsigned dk[3][2];
    for (unsigned i = 0; i < 3; i++) {
        unsigned o0, o1;
        tf2x32(0u, 42u, 0u, i, o0, o1);
        dk[i][0] = o0; dk[i][1] = o1;
    }

    const int TB = 256;
    detect_kernel<<<1, 32>>>((const unsigned*)ei);
    zero_kernel<<<(NN + TB - 1) / TB, TB>>>();
    count_kernel<<<(EE + TB - 1) / TB, TB>>>(ei);
    scan_kernel<<<1, 1024>>>();
    fill_kernel<<<(EE + TB - 1) / TB, TB>>>(ei, ew);

    make_mask_kernel<<<(NWORDS + TB - 1) / TB, TB>>>(dk[0][0], dk[0][1], mask0);
    make_mask_kernel<<<(NWORDS + TB - 1) / TB, TB>>>(dk[1][0], dk[1][1], mask1);
    make_mask_kernel<<<(NWORDS + TB - 1) / TB, TB>>>(dk[2][0], dk[2][1], mask2);

    int gblocks = (NN + 127) / 128;                 // 391
    int wblocks = (NN * 32 + TB - 1) / TB;

    // layer 1
    gemm_kernel<128, false, false, false><<<gblocks, TB>>>(x, nullptr, Wlin_in, blin_in, H, NN, nullptr);
    gather_kernel<<<wblocks, TB>>>(H, AGG);
    gemm_kernel<256, true, true, true><<<gblocks, TB>>>(AGG, x, Wagg_in, bagg_in, B1, NN, mask0);
    // layer 2
    gemm_kernel<128, false, false, false><<<gblocks, TB>>>(B1, nullptr, Wlin_h, blin_h, H, NN, nullptr);
    gather_kernel<<<wblocks, TB>>>(H, AGG);
    gemm_kernel<256, true, true, true><<<gblocks, TB>>>(AGG, B1, Wagg_h, bagg_h, B2, NN, mask1);
    // layer 3 (h straight to d_out)
    gemm_kernel<128, false, false, false><<<gblocks, TB>>>(B2, nullptr, Wlin_h, blin_h, H, NN, nullptr);
    gather_kernel<<<wblocks, TB>>>(H, AGG);
    gemm_kernel<256, true, true, true><<<gblocks, TB>>>(AGG, B2, Wagg_h, bagg_h, out_h, NN, mask2);
    // MLP head
    gemm_kernel<128, false, true, false><<<gblocks, TB>>>(out_h, nullptr, Wm1, bm1, H, NN, nullptr);
    mlp_out_kernel<<<wblocks, TB>>>(H, Wm2, bm2, out_y);
}

// round 6
// speedup vs baseline: 1.9179x; 1.9179x over previous
#include <cuda_runtime.h>
#include <cuda_bf16.h>
#include <cstdint>

// ---------------- problem constants ----------------
#define NN 50000
#define EE 800000
#define DD 128
#define NWORDS 200000   // NN*DD/32
#define NSCAN_BLOCKS 49 // ceil(50000/1024)

// ---------------- device scratch ----------------
__device__ float g_H  [(size_t)NN * DD];
__device__ float g_AGG[(size_t)NN * DD];
__device__ float g_B1 [(size_t)NN * DD];
__device__ float g_B2 [(size_t)NN * DD];
__device__ int   g_cnt[NN];
__device__ int   g_cursor[NN];
__device__ int   g_rowstart[NN + 1];
__device__ float g_inv[NN];
__device__ int   g_bsum[64];
__device__ int   g_boff[64];
__device__ int   g_col[EE];
__device__ float g_w[EE];
__device__ unsigned g_mask[3 * NWORDS];
__device__ int   g_is64;
// transposed + bf16-split weights: Wt[n][k] = W[k][n]
__device__ __nv_bfloat16 g_Wt_hi[131072];
__device__ __nv_bfloat16 g_Wt_lo[131072];
#define OFF_LIN_IN 0
#define OFF_AGG_IN 16384
#define OFF_LIN_H  49152
#define OFF_AGG_H  65536
#define OFF_MLP1   98304

// ---------------- threefry2x32 ----------------
__host__ __device__ inline void tf2x32(unsigned k0, unsigned k1,
                                       unsigned x0, unsigned x1,
                                       unsigned& o0, unsigned& o1) {
    unsigned ks0 = k0, ks1 = k1, ks2 = k0 ^ k1 ^ 0x1BD11BDAu;
    x0 += ks0; x1 += ks1;
#define TFR(r) { x0 += x1; x1 = (x1 << r) | (x1 >> (32 - r)); x1 ^= x0; }
    TFR(13) TFR(15) TFR(26) TFR(6)  x0 += ks1; x1 += ks2 + 1u;
    TFR(17) TFR(29) TFR(16) TFR(24) x0 += ks2; x1 += ks0 + 2u;
    TFR(13) TFR(15) TFR(26) TFR(6)  x0 += ks0; x1 += ks1 + 3u;
    TFR(17) TFR(29) TFR(16) TFR(24) x0 += ks1; x1 += ks2 + 4u;
    TFR(13) TFR(15) TFR(26) TFR(6)  x0 += ks2; x1 += ks0 + 5u;
#undef TFR
    o0 = x0; o1 = x1;
}

__global__ void make_mask_kernel(unsigned k0, unsigned k1, unsigned* mask) {
    unsigned w = blockIdx.x * blockDim.x + threadIdx.x;
    if (w >= NWORDS) return;
    unsigned bits = 0;
#pragma unroll 8
    for (int j = 0; j < 32; j++) {
        unsigned o0, o1;
        tf2x32(k0, k1, 0u, w * 32u + (unsigned)j, o0, o1);
        unsigned draw = o0 ^ o1;
        bits |= ((~draw) >> 31) << j;
    }
    mask[w] = bits;
}

// ---------------- edge dtype ----------------
__global__ void detect_kernel(const unsigned* ei) {
    if (threadIdx.x == 0 && blockIdx.x == 0) {
        int is64 = 1;
        for (int i = 0; i < 64; i++)
            if (ei[2 * i + 1] != 0u) { is64 = 0; break; }
        g_is64 = is64;
    }
}
__device__ __forceinline__ int get_edge(const void* ei, long long i) {
    if (g_is64) return (int)((const long long*)ei)[i];
    return ((const int*)ei)[i];
}

// ---------------- CSR build ----------------
__global__ void zero_kernel() {
    int i = blockIdx.x * blockDim.x + threadIdx.x;
    if (i < NN) { g_cnt[i] = 0; g_cursor[i] = 0; }
}
__global__ void count_kernel(const void* ei) {
    int e = blockIdx.x * blockDim.x + threadIdx.x;
    if (e >= EE) return;
    atomicAdd(&g_cnt[get_edge(ei, e)], 1);
}
__global__ void blockscan_kernel() {
    __shared__ int sh[1024];
    int t = threadIdx.x;
    int i = blockIdx.x * 1024 + t;
    int v = (i < NN) ? g_cnt[i] : 0;
    sh[t] = v;
    __syncthreads();
#pragma unroll
    for (int off = 1; off < 1024; off <<= 1) {
        int add = (t >= off) ? sh[t - off] : 0;
        __syncthreads();
        sh[t] += add;
        __syncthreads();
    }
    if (i < NN) {
        g_rowstart[i] = sh[t] - v;
        g_inv[i] = 1.0f / fmaxf((float)v, 1.0f);
    }
    if (t == 1023) g_bsum[blockIdx.x] = sh[1023];
}
__global__ void scan2_kernel() {
    if (threadIdx.x == 0) {
        int acc = 0;
        for (int b = 0; b < NSCAN_BLOCKS; b++) { g_boff[b] = acc; acc += g_bsum[b]; }
        g_rowstart[NN] = acc;
    }
}
__global__ void addoff_kernel() {
    int i = blockIdx.x * blockDim.x + threadIdx.x;
    if (i < NN) g_rowstart[i] += g_boff[i >> 10];
}
__global__ void fill_kernel(const void* ei, const float* __restrict__ ew) {
    int e = blockIdx.x * blockDim.x + threadIdx.x;
    if (e >= EE) return;
    int r = get_edge(ei, e);
    int c = get_edge(ei, (long long)EE + e);
    int pos = g_rowstart[r] + atomicAdd(&g_cursor[r], 1);
    g_col[pos] = c;
    g_w[pos]   = ew[e];
}

// ---------------- gather aggregation ----------------
__global__ __launch_bounds__(256) void gather_kernel(const float* __restrict__ H,
                                                     float* __restrict__ AGG) {
    int gw = (blockIdx.x * blockDim.x + threadIdx.x) >> 5;
    int lane = threadIdx.x & 31;
    if (gw >= NN) return;
    int s = g_rowstart[gw], e = g_rowstart[gw + 1];
    float4 acc = make_float4(0.f, 0.f, 0.f, 0.f);
    for (int i = s; i < e; i++) {
        int c = g_col[i];
        float ww = g_w[i];
        float4 h4 = __ldg(reinterpret_cast<const float4*>(H + (size_t)c * DD) + lane);
        acc.x += ww * h4.x; acc.y += ww * h4.y;
        acc.z += ww * h4.z; acc.w += ww * h4.w;
    }
    float sc = g_inv[gw];
    acc.x *= sc; acc.y *= sc; acc.z *= sc; acc.w *= sc;
    reinterpret_cast<float4*>(AGG + (size_t)gw * DD)[lane] = acc;
}

// ---------------- weight prep: transpose + bf16 hi/lo split ----------------
__global__ void prep_w_kernel(const float* __restrict__ W,
                              __nv_bfloat16* __restrict__ hi,
                              __nv_bfloat16* __restrict__ lo, int K) {
    int i = blockIdx.x * blockDim.x + threadIdx.x;
    if (i >= K * 128) return;
    int n = i / K, k = i % K;
    float a = W[k * 128 + n];
    __nv_bfloat16 h = __float2bfloat16(a);
    hi[i] = h;
    lo[i] = __float2bfloat16(a - __bfloat162float(h));
}

// ---------------- mma.sync helpers (generic PTX, sm_80-class) ----------------
__device__ __forceinline__ uint32_t smem_u32(const void* p) {
    uint32_t a;
    asm("{ .reg .u64 t; cvta.to.shared.u64 t, %1; cvt.u32.u64 %0, t; }" : "=r"(a) : "l"(p));
    return a;
}
__device__ __forceinline__ void ldsm4(uint32_t* r, uint32_t addr) {
    asm volatile("ldmatrix.sync.aligned.m8n8.x4.shared.b16 {%0,%1,%2,%3}, [%4];"
                 : "=r"(r[0]), "=r"(r[1]), "=r"(r[2]), "=r"(r[3]) : "r"(addr));
}
__device__ __forceinline__ void mma_bf16(float* c, const uint32_t* a, const uint32_t* b) {
    asm volatile("mma.sync.aligned.m16n8k16.row.col.f32.bf16.bf16.f32 "
                 "{%0,%1,%2,%3}, {%4,%5,%6,%7}, {%8,%9}, {%0,%1,%2,%3};"
                 : "+f"(c[0]), "+f"(c[1]), "+f"(c[2]), "+f"(c[3])
                 : "r"(a[0]), "r"(a[1]), "r"(a[2]), "r"(a[3]), "r"(b[0]), "r"(b[1]));
}

// smem layout (bytes). bf16 tiles: 128 rows x 136 halves (padded) = 34816B each
#define TSTRIDE 136
#define SM_AHI  0
#define SM_ALO  34816
#define SM_BHI  69632
#define SM_BLO  104448
#define GEMM_SMEM 139264
// epilogue fp32 buffer reuses smem base: [128][132] = 67584B

// ---------------- tensor-core GEMM: C = [A1 | A2] @ W + bias (+relu,+drop) ----------------
// Wt pre-transposed/split bf16, row stride Kb (n-major: Wt[n][k])
template<int CH, bool RELU, bool DROP>
__global__ __launch_bounds__(256, 1)
void gemm_mma(const float* __restrict__ A1, const float* __restrict__ A2,
              const __nv_bfloat16* __restrict__ Whi, const __nv_bfloat16* __restrict__ Wlo,
              int Kb, const float* __restrict__ bias, float* __restrict__ C,
              const unsigned* __restrict__ mask) {
    extern __shared__ char smem[];
    uint32_t sb = smem_u32(smem);
    int tid = threadIdx.x, wid = tid >> 5, lane = tid & 31;
    int wm = wid & 3, wn = wid >> 2;          // 4x2 warp grid: 32x64 per warp
    int row0 = blockIdx.x * 128;

    float c[2][8][4];
#pragma unroll
    for (int mf = 0; mf < 2; mf++)
#pragma unroll
        for (int nf = 0; nf < 8; nf++)
#pragma unroll
            for (int e = 0; e < 4; e++) c[mf][nf][e] = 0.f;

    // per-lane ldmatrix row/col offsets
    int quad = lane >> 3, qr = lane & 7;
    int a_r = qr + ((quad & 1) << 3);   // +8 row for quads 1,3
    int a_c = (quad & 2) << 2;          // +8 col for quads 2,3
    int b_r = qr + ((quad & 2) << 2);   // +8 row for quads 2,3
    int b_c = (quad & 1) << 3;          // +8 col for quads 1,3

#pragma unroll
    for (int ch = 0; ch < CH; ch++) {
        const float* A = (ch == 0) ? A1 : A2;
        if (ch) __syncthreads();   // protect smem reuse across chunks
        // ---- stage: A fp32 -> bf16 hi/lo; W bf16 direct ----
#pragma unroll
        for (int j = 0; j < 8; j++) {
            int r   = j * 16 + (tid >> 4);
            int col = (tid & 15) * 8;
            uint32_t soff = (uint32_t)(r * TSTRIDE + col) * 2u;
            float av[8];
            int gr = row0 + r;
            if (gr < NN) {
                float4 v0 = *reinterpret_cast<const float4*>(A + (size_t)gr * 128 + col);
                float4 v1 = *reinterpret_cast<const float4*>(A + (size_t)gr * 128 + col + 4);
                av[0]=v0.x; av[1]=v0.y; av[2]=v0.z; av[3]=v0.w;
                av[4]=v1.x; av[5]=v1.y; av[6]=v1.z; av[7]=v1.w;
            } else {
#pragma unroll
                for (int e = 0; e < 8; e++) av[e] = 0.f;
            }
            uint32_t hp[4], lp[4];
#pragma unroll
            for (int e = 0; e < 4; e++) {
                __nv_bfloat162 h2 = __floats2bfloat162_rn(av[2*e], av[2*e+1]);
                float r0 = av[2*e]   - __low2float(h2);
                float r1 = av[2*e+1] - __high2float(h2);
                __nv_bfloat162 l2 = __floats2bfloat162_rn(r0, r1);
                hp[e] = *reinterpret_cast<uint32_t*>(&h2);
                lp[e] = *reinterpret_cast<uint32_t*>(&l2);
            }
            *reinterpret_cast<uint4*>(smem + SM_AHI + soff) = make_uint4(hp[0], hp[1], hp[2], hp[3]);
            *reinterpret_cast<uint4*>(smem + SM_ALO + soff) = make_uint4(lp[0], lp[1], lp[2], lp[3]);
            const uint4* bh = reinterpret_cast<const uint4*>(Whi + (size_t)r * Kb + ch * 128 + col);
            const uint4* bl = reinterpret_cast<const uint4*>(Wlo + (size_t)r * Kb + ch * 128 + col);
            *reinterpret_cast<uint4*>(smem + SM_BHI + soff) = *bh;
            *reinterpret_cast<uint4*>(smem + SM_BLO + soff) = *bl;
        }
        __syncthreads();
        // ---- mainloop: 8 k-steps of 16 ----
#pragma unroll
        for (int ks = 0; ks < 8; ks++) {
            int K0 = ks * 16;
            uint32_t ah[2][4], al[2][4], bh[16], bl[16];
#pragma unroll
            for (int mf = 0; mf < 2; mf++) {
                int R0 = wm * 32 + mf * 16;
                uint32_t off = (uint32_t)((R0 + a_r) * TSTRIDE + K0 + a_c) * 2u;
                ldsm4(ah[mf], sb + SM_AHI + off);
                ldsm4(al[mf], sb + SM_ALO + off);
            }
#pragma unroll
            for (int p = 0; p < 4; p++) {
                int N0 = wn * 64 + p * 16;
                uint32_t off = (uint32_t)((N0 + b_r) * TSTRIDE + K0 + b_c) * 2u;
                ldsm4(&bh[4 * p], sb + SM_BHI + off);
                ldsm4(&bl[4 * p], sb + SM_BLO + off);
            }
            // 3 passes ordered so same-accumulator mmas are 16 apart
#pragma unroll
            for (int mf = 0; mf < 2; mf++)
#pragma unroll
                for (int nf = 0; nf < 8; nf++)
                    mma_bf16(c[mf][nf], ah[mf], &bh[2 * nf]);
#pragma unroll
            for (int mf = 0; mf < 2; mf++)
#pragma unroll
                for (int nf = 0; nf < 8; nf++)
                    mma_bf16(c[mf][nf], ah[mf], &bl[2 * nf]);
#pragma unroll
            for (int mf = 0; mf < 2; mf++)
#pragma unroll
                for (int nf = 0; nf < 8; nf++)
                    mma_bf16(c[mf][nf], al[mf], &bh[2 * nf]);
        }
    }
    __syncthreads();   // all ldmatrix done; reuse smem as fp32 epi buffer

    // ---- epilogue: bias/relu/dropout into smem, then coalesced store ----
    float* epi = reinterpret_cast<float*>(smem);
    int lr = lane >> 2, lc = (lane & 3) * 2;
#pragma unroll
    for (int mf = 0; mf < 2; mf++) {
#pragma unroll
        for (int nf = 0; nf < 8; nf++) {
            int col = wn * 64 + nf * 8 + lc;
            float bi0 = __ldg(bias + col), bi1 = __ldg(bias + col + 1);
#pragma unroll
            for (int h = 0; h < 2; h++) {
                int row = wm * 32 + mf * 16 + lr + h * 8;
                int gr = row0 + row;
                float v0 = c[mf][nf][2 * h]     + bi0;
                float v1 = c[mf][nf][2 * h + 1] + bi1;
                if (RELU) { v0 = fmaxf(v0, 0.f); v1 = fmaxf(v1, 0.f); }
                if (DROP) {
                    unsigned m = (gr < NN) ? mask[(unsigned)gr * 4u + (unsigned)(col >> 5)] : 0u;
                    v0 = ((m >> (col & 31)) & 1u) ? v0 * 2.f : 0.f;
                    v1 = ((m >> ((col + 1) & 31)) & 1u) ? v1 * 2.f : 0.f;
                }
                epi[row * 132 + col]     = v0;
                epi[row * 132 + col + 1] = v1;
            }
        }
    }
    __syncthreads();
#pragma unroll
    for (int j = 0; j < 8; j++) {
        int rr = j * 16 + (tid >> 4);
        int col = (tid & 15) * 8;
        int g = row0 + rr;
        if (g < NN) {
            float4 o0 = *reinterpret_cast<float4*>(epi + rr * 132 + col);
            float4 o1 = *reinterpret_cast<float4*>(epi + rr * 132 + col + 4);
            *reinterpret_cast<float4*>(C + (size_t)g * 128 + col) = o0;
            *reinterpret_cast<float4*>(C + (size_t)g * 128 + col + 4) = o1;
        }
    }
}

// ---------------- final tiny GEMM: Y = T @ W2(128x10) + b2 ----------------
__global__ __launch_bounds__(256) void mlp_out_kernel(const float* __restrict__ T,
                                                      const float* __restrict__ W2,
                                                      const float* __restrict__ b2,
                                                      float* __restrict__ Y) {
    __shared__ float w2s[1280];
    __shared__ float b2s[10];
    int tid = threadIdx.x;
    for (int i = tid; i < 1280; i += blockDim.x) w2s[i] = W2[i];
    if (tid < 10) b2s[tid] = b2[tid];
    __syncthreads();
    int gw = (blockIdx.x * blockDim.x + tid) >> 5;
    int lane = tid & 31;
    if (gw >= NN) return;
    float4 t4 = *reinterpret_cast<const float4*>(T + (size_t)gw * 128 + lane * 4);
    float a[10];
#pragma unroll
    for (int c = 0; c < 10; c++) {
        a[c] = t4.x * w2s[(lane * 4 + 0) * 10 + c]
             + t4.y * w2s[(lane * 4 + 1) * 10 + c]
             + t4.z * w2s[(lane * 4 + 2) * 10 + c]
             + t4.w * w2s[(lane * 4 + 3) * 10 + c];
    }
#pragma unroll
    for (int c = 0; c < 10; c++) {
        float v = a[c];
        v += __shfl_xor_sync(0xffffffffu, v, 16);
        v += __shfl_xor_sync(0xffffffffu, v, 8);
        v += __shfl_xor_sync(0xffffffffu, v, 4);
        v += __shfl_xor_sync(0xffffffffu, v, 2);
        v += __shfl_xor_sync(0xffffffffu, v, 1);
        if (lane == 0) Y[(size_t)gw * 10 + c] = v + b2s[c];
    }
}

// ---------------- host launch ----------------
extern "C" void kernel_launch(void* const* d_in, const int* in_sizes, int n_in,
                              void* d_out, int out_size) {
    const float* x       = (const float*)d_in[0];
    const void*  ei      = d_in[1];
    const float* ew      = (const float*)d_in[2];
    const float* Wlin_in = (const float*)d_in[3];
    const float* blin_in = (const float*)d_in[4];
    const float* Wagg_in = (const float*)d_in[5];
    const float* bagg_in = (const float*)d_in[6];
    const float* Wlin_h  = (const float*)d_in[7];
    const float* blin_h  = (const float*)d_in[8];
    const float* Wagg_h  = (const float*)d_in[9];
    const float* bagg_h  = (const float*)d_in[10];
    const float* Wm1     = (const float*)d_in[11];
    const float* bm1     = (const float*)d_in[12];
    const float* Wm2     = (const float*)d_in[13];
    const float* bm2     = (const float*)d_in[14];

    float* out_h = (float*)d_out;
    float* out_y = out_h + (size_t)NN * DD;

    void *pH, *pAGG, *pB1, *pB2, *pMask, *pWhi, *pWlo;
    cudaGetSymbolAddress(&pH, g_H);
    cudaGetSymbolAddress(&pAGG, g_AGG);
    cudaGetSymbolAddress(&pB1, g_B1);
    cudaGetSymbolAddress(&pB2, g_B2);
    cudaGetSymbolAddress(&pMask, g_mask);
    cudaGetSymbolAddress(&pWhi, g_Wt_hi);
    cudaGetSymbolAddress(&pWlo, g_Wt_lo);
    float* H   = (float*)pH;
    float* AGG = (float*)pAGG;
    float* B1  = (float*)pB1;
    float* B2  = (float*)pB2;
    unsigned* mask0 = (unsigned*)pMask;
    unsigned* mask1 = mask0 + NWORDS;
    unsigned* mask2 = mask0 + 2 * NWORDS;
    __nv_bfloat16* Whi = (__nv_bfloat16*)pWhi;
    __nv_bfloat16* Wlo = (__nv_bfloat16*)pWlo;

    cudaFuncSetAttribute(gemm_mma<1, false, false>, cudaFuncAttributeMaxDynamicSharedMemorySize, GEMM_SMEM);
    cudaFuncSetAttribute(gemm_mma<2, true, true>,   cudaFuncAttributeMaxDynamicSharedMemorySize, GEMM_SMEM);
    cudaFuncSetAttribute(gemm_mma<1, true, false>,  cudaFuncAttributeMaxDynamicSharedMemorySize, GEMM_SMEM);

    unsigned dk[3][2];
    for (unsigned i = 0; i < 3; i++) {
        unsigned o0, o1;
        tf2x32(0u, 42u, 0u, i, o0, o1);
        dk[i][0] = o0; dk[i][1] = o1;
    }

    const int TB = 256;
    detect_kernel<<<1, 32>>>((const unsigned*)ei);
    zero_kernel<<<(NN + TB - 1) / TB, TB>>>();
    count_kernel<<<(EE + TB - 1) / TB, TB>>>(ei);
    blockscan_kernel<<<NSCAN_BLOCKS, 1024>>>();
    scan2_kernel<<<1, 32>>>();
    addoff_kernel<<<(NN + TB - 1) / TB, TB>>>();
    fill_kernel<<<(EE + TB - 1) / TB, TB>>>(ei, ew);

    make_mask_kernel<<<(NWORDS + TB - 1) / TB, TB>>>(dk[0][0], dk[0][1], mask0);
    make_mask_kernel<<<(NWORDS + TB - 1) / TB, TB>>>(dk[1][0], dk[1][1], mask1);
    make_mask_kernel<<<(NWORDS + TB - 1) / TB, TB>>>(dk[2][0], dk[2][1], mask2);

    prep_w_kernel<<<(128 * 128 + TB - 1) / TB, TB>>>(Wlin_in, Whi + OFF_LIN_IN, Wlo + OFF_LIN_IN, 128);
    prep_w_kernel<<<(128 * 256 + TB - 1) / TB, TB>>>(Wagg_in, Whi + OFF_AGG_IN, Wlo + OFF_AGG_IN, 256);
    prep_w_kernel<<<(128 * 128 + TB - 1) / TB, TB>>>(Wlin_h,  Whi + OFF_LIN_H,  Wlo + OFF_LIN_H,  128);
    prep_w_kernel<<<(128 * 256 + TB - 1) / TB, TB>>>(Wagg_h,  Whi + OFF_AGG_H,  Wlo + OFF_AGG_H,  256);
    prep_w_kernel<<<(128 * 128 + TB - 1) / TB, TB>>>(Wm1,     Whi + OFF_MLP1,   Wlo + OFF_MLP1,   128);

    int gblocks = (NN + 127) / 128;         // 391
    int wblocks = (NN * 32 + TB - 1) / TB;

    // layer 1
    gemm_mma<1, false, false><<<gblocks, TB, GEMM_SMEM>>>(x, nullptr, Whi + OFF_LIN_IN, Wlo + OFF_LIN_IN, 128, blin_in, H, nullptr);
    gather_kernel<<<wblocks, TB>>>(H, AGG);
    gemm_mma<2, true, true><<<gblocks, TB, GEMM_SMEM>>>(AGG, x, Whi + OFF_AGG_IN, Wlo + OFF_AGG_IN, 256, bagg_in, B1, mask0);
    // layer 2
    gemm_mma<1, false, false><<<gblocks, TB, GEMM_SMEM>>>(B1, nullptr, Whi + OFF_LIN_H, Wlo + OFF_LIN_H, 128, blin_h, H, nullptr);
    gather_kernel<<<wblocks, TB>>>(H, AGG);
    gemm_mma<2, true, true><<<gblocks, TB, GEMM_SMEM>>>(AGG, B1, Whi + OFF_AGG_H, Wlo + OFF_AGG_H, 256, bagg_h, B2, mask1);
    // layer 3 (h -> d_out)
    gemm_mma<1, false, false><<<gblocks, TB, GEMM_SMEM>>>(B2, nullptr, Whi + OFF_LIN_H, Wlo + OFF_LIN_H, 128, blin_h, H, nullptr);
    gather_kernel<<<wblocks, TB>>>(H, AGG);
    gemm_mma<2, true, true><<<gblocks, TB, GEMM_SMEM>>>(AGG, B2, Whi + OFF_AGG_H, Wlo + OFF_AGG_H, 256, bagg_h, out_h, mask2);
    // MLP head
    gemm_mma<1, true, false><<<gblocks, TB, GEMM_SMEM>>>(out_h, nullptr, Whi + OFF_MLP1, Wlo + OFF_MLP1, 128, bm1, H, nullptr);
    mlp_out_kernel<<<wblocks, TB>>>(H, Wm2, bm2, out_y);
}

// round 7
// speedup vs baseline: 2.2758x; 1.1866x over previous
#include <cuda_runtime.h>
#include <cuda_bf16.h>
#include <cstdint>

// ---------------- problem constants ----------------
#define NN 50000
#define EE 800000
#define DD 128
#define NWORDS 200000   // NN*DD/32
#define NSCAN_BLOCKS 49 // ceil(50000/1024)

// ---------------- device scratch ----------------
__device__ float g_H  [(size_t)NN * DD];
__device__ float g_AGG[(size_t)NN * DD];
__device__ float g_B1 [(size_t)NN * DD];
__device__ float g_B2 [(size_t)NN * DD];
__device__ float g_s  [NN];
__device__ int   g_cnt[NN];
__device__ int   g_cursor[NN];
__device__ int   g_rowstart[NN + 1];
__device__ float g_inv[NN];
__device__ int   g_bsum[64];
__device__ int   g_boff[64];
__device__ int   g_col[EE];
__device__ float g_w[EE];
__device__ unsigned g_mask[3 * NWORDS];
__device__ int   g_is64;
// fused weights, transposed + bf16 hi/lo split: Wt[n][k]
__device__ __nv_bfloat16 g_Wt_hi[131072];
__device__ __nv_bfloat16 g_Wt_lo[131072];
__device__ float g_bv[2][128];
// element offsets: agg_in (256K rows fused), agg_h, mlp1
#define OFF_AGG_IN 0
#define OFF_AGG_H  32768
#define OFF_MLP1   65536

// ---------------- threefry2x32 ----------------
__host__ __device__ inline void tf2x32(unsigned k0, unsigned k1,
                                       unsigned x0, unsigned x1,
                                       unsigned& o0, unsigned& o1) {
    unsigned ks0 = k0, ks1 = k1, ks2 = k0 ^ k1 ^ 0x1BD11BDAu;
    x0 += ks0; x1 += ks1;
#define TFR(r) { x0 += x1; x1 = (x1 << r) | (x1 >> (32 - r)); x1 ^= x0; }
    TFR(13) TFR(15) TFR(26) TFR(6)  x0 += ks1; x1 += ks2 + 1u;
    TFR(17) TFR(29) TFR(16) TFR(24) x0 += ks2; x1 += ks0 + 2u;
    TFR(13) TFR(15) TFR(26) TFR(6)  x0 += ks0; x1 += ks1 + 3u;
    TFR(17) TFR(29) TFR(16) TFR(24) x0 += ks1; x1 += ks2 + 4u;
    TFR(13) TFR(15) TFR(26) TFR(6)  x0 += ks2; x1 += ks0 + 5u;
#undef TFR
    o0 = x0; o1 = x1;
}

__global__ void make_mask_kernel(unsigned k0, unsigned k1, unsigned* mask) {
    unsigned w = blockIdx.x * blockDim.x + threadIdx.x;
    if (w >= NWORDS) return;
    unsigned bits = 0;
#pragma unroll 8
    for (int j = 0; j < 32; j++) {
        unsigned o0, o1;
        tf2x32(k0, k1, 0u, w * 32u + (unsigned)j, o0, o1);
        unsigned draw = o0 ^ o1;
        bits |= ((~draw) >> 31) << j;
    }
    mask[w] = bits;
}

// ---------------- edge dtype ----------------
__global__ void detect_kernel(const unsigned* ei) {
    if (threadIdx.x == 0 && blockIdx.x == 0) {
        int is64 = 1;
        for (int i = 0; i < 64; i++)
            if (ei[2 * i + 1] != 0u) { is64 = 0; break; }
        g_is64 = is64;
    }
}
__device__ __forceinline__ int get_edge(const void* ei, long long i) {
    if (g_is64) return (int)((const long long*)ei)[i];
    return ((const int*)ei)[i];
}

// ---------------- CSR build ----------------
__global__ void zero_kernel() {
    int i = blockIdx.x * blockDim.x + threadIdx.x;
    if (i < NN) { g_cnt[i] = 0; g_cursor[i] = 0; }
}
__global__ void count_kernel(const void* ei) {
    int e = blockIdx.x * blockDim.x + threadIdx.x;
    if (e >= EE) return;
    atomicAdd(&g_cnt[get_edge(ei, e)], 1);
}
__global__ void blockscan_kernel() {
    __shared__ int sh[1024];
    int t = threadIdx.x;
    int i = blockIdx.x * 1024 + t;
    int v = (i < NN) ? g_cnt[i] : 0;
    sh[t] = v;
    __syncthreads();
#pragma unroll
    for (int off = 1; off < 1024; off <<= 1) {
        int add = (t >= off) ? sh[t - off] : 0;
        __syncthreads();
        sh[t] += add;
        __syncthreads();
    }
    if (i < NN) {
        g_rowstart[i] = sh[t] - v;
        g_inv[i] = 1.0f / fmaxf((float)v, 1.0f);
    }
    if (t == 1023) g_bsum[blockIdx.x] = sh[1023];
}
__global__ void scan2_kernel() {
    if (threadIdx.x == 0) {
        int acc = 0;
        for (int b = 0; b < NSCAN_BLOCKS; b++) { g_boff[b] = acc; acc += g_bsum[b]; }
        g_rowstart[NN] = acc;
    }
}
__global__ void addoff_kernel() {
    int i = blockIdx.x * blockDim.x + threadIdx.x;
    if (i < NN) g_rowstart[i] += g_boff[i >> 10];
}
__global__ void fill_kernel(const void* ei, const float* __restrict__ ew) {
    int e = blockIdx.x * blockDim.x + threadIdx.x;
    if (e >= EE) return;
    int r = get_edge(ei, e);
    int c = get_edge(ei, (long long)EE + e);
    int pos = g_rowstart[r] + atomicAdd(&g_cursor[r], 1);
    g_col[pos] = c;
    g_w[pos]   = ew[e];
}

// ---------------- gather: AGG = mean(ew * SRC[col]); also s = mean(ew) ----------------
__global__ __launch_bounds__(256) void gather_kernel(const float* __restrict__ SRC,
                                                     float* __restrict__ AGG) {
    int gw = (blockIdx.x * blockDim.x + threadIdx.x) >> 5;
    int lane = threadIdx.x & 31;
    if (gw >= NN) return;
    int s = g_rowstart[gw], e = g_rowstart[gw + 1];
    float4 acc = make_float4(0.f, 0.f, 0.f, 0.f);
    float ws = 0.f;
    for (int i = s; i < e; i++) {
        int c = g_col[i];
        float ww = g_w[i];
        ws += ww;
        float4 h4 = __ldg(reinterpret_cast<const float4*>(SRC + (size_t)c * DD) + lane);
        acc.x += ww * h4.x; acc.y += ww * h4.y;
        acc.z += ww * h4.z; acc.w += ww * h4.w;
    }
    float sc = g_inv[gw];
    acc.x *= sc; acc.y *= sc; acc.z *= sc; acc.w *= sc;
    reinterpret_cast<float4*>(AGG + (size_t)gw * DD)[lane] = acc;
    if (lane == 0) g_s[gw] = ws * sc;
}

// ---------------- weight prep ----------------
// plain transpose + split (for mlp1 and W_agg bottom half)
__global__ void prep_w_kernel(const float* __restrict__ W,
                              __nv_bfloat16* __restrict__ hi,
                              __nv_bfloat16* __restrict__ lo,
                              int Kb, int koff) {
    int i = blockIdx.x * blockDim.x + threadIdx.x;
    if (i >= 128 * 128) return;
    int n = i / 128, k = i % 128;
    float a = W[k * 128 + n];
    __nv_bfloat16 h = __float2bfloat16(a);
    hi[n * Kb + koff + k] = h;
    lo[n * Kb + koff + k] = __float2bfloat16(a - __bfloat162float(h));
}
// fused top: Wc[k][n] = sum_m W_lin[k][m] * W_agg_top[m][n]; store transposed at [n*256 + k]
__global__ void prep_wc_kernel(const float* __restrict__ Wlin,
                               const float* __restrict__ Wagg,
                               __nv_bfloat16* __restrict__ hi,
                               __nv_bfloat16* __restrict__ lo) {
    __shared__ float colv[128];
    int n = blockIdx.x, k = threadIdx.x;
    colv[k] = Wagg[k * 128 + n];   // W_agg_top[m=k][n]
    __syncthreads();
    float acc = 0.f;
    const float* wr = Wlin + k * 128;
#pragma unroll 8
    for (int m = 0; m < 128; m++) acc += wr[m] * colv[m];
    __nv_bfloat16 h = __float2bfloat16(acc);
    hi[n * 256 + k] = h;
    lo[n * 256 + k] = __float2bfloat16(acc - __bfloat162float(h));
}
// bv[n] = sum_m b_lin[m] * W_agg_top[m][n]
__global__ void prep_bv_kernel(const float* __restrict__ blin,
                               const float* __restrict__ Wagg, float* __restrict__ bv) {
    int n = threadIdx.x;
    float acc = 0.f;
    for (int m = 0; m < 128; m++) acc += blin[m] * Wagg[m * 128 + n];
    bv[n] = acc;
}

// ---------------- mma.sync helpers ----------------
__device__ __forceinline__ uint32_t smem_u32(const void* p) {
    uint32_t a;
    asm("{ .reg .u64 t; cvta.to.shared.u64 t, %1; cvt.u32.u64 %0, t; }" : "=r"(a) : "l"(p));
    return a;
}
__device__ __forceinline__ void ldsm4(uint32_t* r, uint32_t addr) {
    asm volatile("ldmatrix.sync.aligned.m8n8.x4.shared.b16 {%0,%1,%2,%3}, [%4];"
                 : "=r"(r[0]), "=r"(r[1]), "=r"(r[2]), "=r"(r[3]) : "r"(addr));
}
__device__ __forceinline__ void mma_bf16(float* c, const uint32_t* a, const uint32_t* b) {
    asm volatile("mma.sync.aligned.m16n8k16.row.col.f32.bf16.bf16.f32 "
                 "{%0,%1,%2,%3}, {%4,%5,%6,%7}, {%8,%9}, {%0,%1,%2,%3};"
                 : "+f"(c[0]), "+f"(c[1]), "+f"(c[2]), "+f"(c[3])
                 : "r"(a[0]), "r"(a[1]), "r"(a[2]), "r"(a[3]), "r"(b[0]), "r"(b[1]));
}

#define TSTRIDE 136
#define SM_AHI  0
#define SM_ALO  34816
#define SM_BHI  69632
#define SM_BLO  104448
#define GEMM_SMEM 139264

// ---------------- tensor-core GEMM: C = [A1 | A2] @ Wt + bias (+s*bv, relu, drop) ----------
// 512 threads, 4x4 warp grid, 32x32 per warp
template<int CH, bool RELU, bool DROP, bool SBV>
__global__ __launch_bounds__(512, 1)
void gemm_mma(const float* __restrict__ A1, const float* __restrict__ A2,
              const __nv_bfloat16* __restrict__ Whi, const __nv_bfloat16* __restrict__ Wlo,
              int Kb, const float* __restrict__ bias, const float* __restrict__ bv,
              float* __restrict__ C, const unsigned* __restrict__ mask) {
    extern __shared__ char smem[];
    uint32_t sb = smem_u32(smem);
    int tid = threadIdx.x, wid = tid >> 5, lane = tid & 31;
    int wm = wid & 3, wn = wid >> 2;          // 4x4 warp grid: 32x32 per warp
    int row0 = blockIdx.x * 128;

    float c[2][4][4];
#pragma unroll
    for (int mf = 0; mf < 2; mf++)
#pragma unroll
        for (int nf = 0; nf < 4; nf++)
#pragma unroll
            for (int e = 0; e < 4; e++) c[mf][nf][e] = 0.f;

    int quad = lane >> 3, qr = lane & 7;
    int a_r = qr + ((quad & 1) << 3);
    int a_c = (quad & 2) << 2;
    int b_r = qr + ((quad & 2) << 2);
    int b_c = (quad & 1) << 3;

#pragma unroll
    for (int ch = 0; ch < CH; ch++) {
        const float* A = (ch == 0) ? A1 : A2;
        if (ch) __syncthreads();
        // ---- stage: A fp32 -> bf16 hi/lo; W bf16 direct ----
#pragma unroll
        for (int j = 0; j < 4; j++) {
            int r   = j * 32 + (tid >> 4);
            int col = (tid & 15) * 8;
            uint32_t soff = (uint32_t)(r * TSTRIDE + col) * 2u;
            float av[8];
            int gr = row0 + r;
            if (gr < NN) {
                float4 v0 = *reinterpret_cast<const float4*>(A + (size_t)gr * 128 + col);
                float4 v1 = *reinterpret_cast<const float4*>(A + (size_t)gr * 128 + col + 4);
                av[0]=v0.x; av[1]=v0.y; av[2]=v0.z; av[3]=v0.w;
                av[4]=v1.x; av[5]=v1.y; av[6]=v1.z; av[7]=v1.w;
            } else {
#pragma unroll
                for (int e = 0; e < 8; e++) av[e] = 0.f;
            }
            uint32_t hp[4], lp[4];
#pragma unroll
            for (int e = 0; e < 4; e++) {
                __nv_bfloat162 h2 = __floats2bfloat162_rn(av[2*e], av[2*e+1]);
                float r0 = av[2*e]   - __low2float(h2);
                float r1 = av[2*e+1] - __high2float(h2);
                __nv_bfloat162 l2 = __floats2bfloat162_rn(r0, r1);
                hp[e] = *reinterpret_cast<uint32_t*>(&h2);
                lp[e] = *reinterpret_cast<uint32_t*>(&l2);
            }
            *reinterpret_cast<uint4*>(smem + SM_AHI + soff) = make_uint4(hp[0], hp[1], hp[2], hp[3]);
            *reinterpret_cast<uint4*>(smem + SM_ALO + soff) = make_uint4(lp[0], lp[1], lp[2], lp[3]);
            const uint4* bh = reinterpret_cast<const uint4*>(Whi + (size_t)r * Kb + ch * 128 + col);
            const uint4* bl = reinterpret_cast<const uint4*>(Wlo + (size_t)r * Kb + ch * 128 + col);
            *reinterpret_cast<uint4*>(smem + SM_BHI + soff) = *bh;
            *reinterpret_cast<uint4*>(smem + SM_BLO + soff) = *bl;
        }
        __syncthreads();
        // ---- mainloop: 8 k-steps of 16 ----
#pragma unroll
        for (int ks = 0; ks < 8; ks++) {
            int K0 = ks * 16;
            uint32_t ah[2][4], al[2][4], bh[8], bl[8];
#pragma unroll
            for (int mf = 0; mf < 2; mf++) {
                int R0 = wm * 32 + mf * 16;
                uint32_t off = (uint32_t)((R0 + a_r) * TSTRIDE + K0 + a_c) * 2u;
                ldsm4(ah[mf], sb + SM_AHI + off);
                ldsm4(al[mf], sb + SM_ALO + off);
            }
#pragma unroll
            for (int p = 0; p < 2; p++) {
                int N0 = wn * 32 + p * 16;
                uint32_t off = (uint32_t)((N0 + b_r) * TSTRIDE + K0 + b_c) * 2u;
                ldsm4(&bh[4 * p], sb + SM_BHI + off);
                ldsm4(&bl[4 * p], sb + SM_BLO + off);
            }
#pragma unroll
            for (int mf = 0; mf < 2; mf++)
#pragma unroll
                for (int nf = 0; nf < 4; nf++)
                    mma_bf16(c[mf][nf], ah[mf], &bh[2 * nf]);
#pragma unroll
            for (int mf = 0; mf < 2; mf++)
#pragma unroll
                for (int nf = 0; nf < 4; nf++)
                    mma_bf16(c[mf][nf], ah[mf], &bl[2 * nf]);
#pragma unroll
            for (int mf = 0; mf < 2; mf++)
#pragma unroll
                for (int nf = 0; nf < 4; nf++)
                    mma_bf16(c[mf][nf], al[mf], &bh[2 * nf]);
        }
    }
    __syncthreads();   // reuse smem as fp32 epi buffer

    // ---- epilogue ----
    float* epi = reinterpret_cast<float*>(smem);
    int lr = lane >> 2, lc = (lane & 3) * 2;
#pragma unroll
    for (int mf = 0; mf < 2; mf++) {
#pragma unroll
        for (int nf = 0; nf < 4; nf++) {
            int col = wn * 32 + nf * 8 + lc;
            float bi0 = __ldg(bias + col), bi1 = __ldg(bias + col + 1);
            float bv0 = 0.f, bv1 = 0.f;
            if (SBV) { bv0 = __ldg(bv + col); bv1 = __ldg(bv + col + 1); }
#pragma unroll
            for (int h = 0; h < 2; h++) {
                int row = wm * 32 + mf * 16 + lr + h * 8;
                int gr = row0 + row;
                float sval = (SBV && gr < NN) ? g_s[gr] : 0.f;
                float v0 = c[mf][nf][2 * h]     + bi0;
                float v1 = c[mf][nf][2 * h + 1] + bi1;
                if (SBV) { v0 += sval * bv0; v1 += sval * bv1; }
                if (RELU) { v0 = fmaxf(v0, 0.f); v1 = fmaxf(v1, 0.f); }
                if (DROP) {
                    unsigned m = (gr < NN) ? mask[(unsigned)gr * 4u + (unsigned)(col >> 5)] : 0u;
                    v0 = ((m >> (col & 31)) & 1u) ? v0 * 2.f : 0.f;
                    v1 = ((m >> ((col + 1) & 31)) & 1u) ? v1 * 2.f : 0.f;
                }
                epi[row * 132 + col]     = v0;
                epi[row * 132 + col + 1] = v1;
            }
        }
    }
    __syncthreads();
#pragma unroll
    for (int j = 0; j < 4; j++) {
        int rr = j * 32 + (tid >> 4);
        int col = (tid & 15) * 8;
        int g = row0 + rr;
        if (g < NN) {
            float4 o0 = *reinterpret_cast<float4*>(epi + rr * 132 + col);
            float4 o1 = *reinterpret_cast<float4*>(epi + rr * 132 + col + 4);
            *reinterpret_cast<float4*>(C + (size_t)g * 128 + col) = o0;
            *reinterpret_cast<float4*>(C + (size_t)g * 128 + col + 4) = o1;
        }
    }
}

// ---------------- final tiny GEMM: Y = T @ W2(128x10) + b2 ----------------
__global__ __launch_bounds__(256) void mlp_out_kernel(const float* __restrict__ T,
                                                      const float* __restrict__ W2,
                                                      const float* __restrict__ b2,
                                                      float* __restrict__ Y) {
    __shared__ float w2s[1280];
    __shared__ float b2s[10];
    int tid = threadIdx.x;
    for (int i = tid; i < 1280; i += blockDim.x) w2s[i] = W2[i];
    if (tid < 10) b2s[tid] = b2[tid];
    __syncthreads();
    int gw = (blockIdx.x * blockDim.x + tid) >> 5;
    int lane = tid & 31;
    if (gw >= NN) return;
    float4 t4 = *reinterpret_cast<const float4*>(T + (size_t)gw * 128 + lane * 4);
    float a[10];
#pragma unroll
    for (int c = 0; c < 10; c++) {
        a[c] = t4.x * w2s[(lane * 4 + 0) * 10 + c]
             + t4.y * w2s[(lane * 4 + 1) * 10 + c]
             + t4.z * w2s[(lane * 4 + 2) * 10 + c]
             + t4.w * w2s[(lane * 4 + 3) * 10 + c];
    }
#pragma unroll
    for (int c = 0; c < 10; c++) {
        float v = a[c];
        v += __shfl_xor_sync(0xffffffffu, v, 16);
        v += __shfl_xor_sync(0xffffffffu, v, 8);
        v += __shfl_xor_sync(0xffffffffu, v, 4);
        v += __shfl_xor_sync(0xffffffffu, v, 2);
        v += __shfl_xor_sync(0xffffffffu, v, 1);
        if (lane == 0) Y[(size_t)gw * 10 + c] = v + b2s[c];
    }
}

// ---------------- host launch ----------------
extern "C" void kernel_launch(void* const* d_in, const int* in_sizes, int n_in,
                              void* d_out, int out_size) {
    const float* x       = (const float*)d_in[0];
    const void*  ei      = d_in[1];
    const float* ew      = (const float*)d_in[2];
    const float* Wlin_in = (const float*)d_in[3];
    const float* blin_in = (const float*)d_in[4];
    const float* Wagg_in = (const float*)d_in[5];
    const float* bagg_in = (const float*)d_in[6];
    const float* Wlin_h  = (const float*)d_in[7];
    const float* blin_h  = (const float*)d_in[8];
    const float* Wagg_h  = (const float*)d_in[9];
    const float* bagg_h  = (const float*)d_in[10];
    const float* Wm1     = (const float*)d_in[11];
    const float* bm1     = (const float*)d_in[12];
    const float* Wm2     = (const float*)d_in[13];
    const float* bm2     = (const float*)d_in[14];

    float* out_h = (float*)d_out;
    float* out_y = out_h + (size_t)NN * DD;

    void *pH, *pAGG, *pB1, *pB2, *pMask, *pWhi, *pWlo, *pBv;
    cudaGetSymbolAddress(&pH, g_H);
    cudaGetSymbolAddress(&pAGG, g_AGG);
    cudaGetSymbolAddress(&pB1, g_B1);
    cudaGetSymbolAddress(&pB2, g_B2);
    cudaGetSymbolAddress(&pMask, g_mask);
    cudaGetSymbolAddress(&pWhi, g_Wt_hi);
    cudaGetSymbolAddress(&pWlo, g_Wt_lo);
    cudaGetSymbolAddress(&pBv, g_bv);
    float* H   = (float*)pH;
    float* AGG = (float*)pAGG;
    float* B1  = (float*)pB1;
    float* B2  = (float*)pB2;
    unsigned* mask0 = (unsigned*)pMask;
    unsigned* mask1 = mask0 + NWORDS;
    unsigned* mask2 = mask0 + 2 * NWORDS;
    __nv_bfloat16* Whi = (__nv_bfloat16*)pWhi;
    __nv_bfloat16* Wlo = (__nv_bfloat16*)pWlo;
    float* bv0 = (float*)pBv;
    float* bv1 = bv0 + 128;

    cudaFuncSetAttribute(gemm_mma<2, true, true, true>,   cudaFuncAttributeMaxDynamicSharedMemorySize, GEMM_SMEM);
    cudaFuncSetAttribute(gemm_mma<1, true, false, false>, cudaFuncAttributeMaxDynamicSharedMemorySize, GEMM_SMEM);

    unsigned dk[3][2];
    for (unsigned i = 0; i < 3; i++) {
        unsigned o0, o1;
        tf2x32(0u, 42u, 0u, i, o0, o1);
        dk[i][0] = o0; dk[i][1] = o1;
    }

    const int TB = 256;
    detect_kernel<<<1, 32>>>((const unsigned*)ei);
    zero_kernel<<<(NN + TB - 1) / TB, TB>>>();
    count_kernel<<<(EE + TB - 1) / TB, TB>>>(ei);
    blockscan_kernel<<<NSCAN_BLOCKS, 1024>>>();
    scan2_kernel<<<1, 32>>>();
    addoff_kernel<<<(NN + TB - 1) / TB, TB>>>();
    fill_kernel<<<(EE + TB - 1) / TB, TB>>>(ei, ew);

    make_mask_kernel<<<(NWORDS + TB - 1) / TB, TB>>>(dk[0][0], dk[0][1], mask0);
    make_mask_kernel<<<(NWORDS + TB - 1) / TB, TB>>>(dk[1][0], dk[1][1], mask1);
    make_mask_kernel<<<(NWORDS + TB - 1) / TB, TB>>>(dk[2][0], dk[2][1], mask2);

    // fused weight prep:
    //   top half (k in [0,128)): Wc = W_lin @ W_agg_top, transposed+split
    //   bottom half (k in [128,256)): W_agg rows 128..255, transposed+split
    prep_wc_kernel<<<128, 128>>>(Wlin_in, Wagg_in, Whi + OFF_AGG_IN, Wlo + OFF_AGG_IN);
    prep_w_kernel<<<(128 * 128 + TB - 1) / TB, TB>>>(Wagg_in + 128 * 128, Whi + OFF_AGG_IN, Wlo + OFF_AGG_IN, 256, 128);
    prep_bv_kernel<<<1, 128>>>(blin_in, Wagg_in, bv0);
    prep_wc_kernel<<<128, 128>>>(Wlin_h, Wagg_h, Whi + OFF_AGG_H, Wlo + OFF_AGG_H);
    prep_w_kernel<<<(128 * 128 + TB - 1) / TB, TB>>>(Wagg_h + 128 * 128, Whi + OFF_AGG_H, Wlo + OFF_AGG_H, 256, 128);
    prep_bv_kernel<<<1, 128>>>(blin_h, Wagg_h, bv1);
    prep_w_kernel<<<(128 * 128 + TB - 1) / TB, TB>>>(Wm1, Whi + OFF_MLP1, Wlo + OFF_MLP1, 128, 0);

    int gblocks = (NN + 127) / 128;         // 391
    int wblocks = (NN * 32 + TB - 1) / TB;

    // layer 1: agg on raw x, fused GEMM
    gather_kernel<<<wblocks, TB>>>(x, AGG);
    gemm_mma<2, true, true, true><<<gblocks, 512, GEMM_SMEM>>>(AGG, x, Whi + OFF_AGG_IN, Wlo + OFF_AGG_IN, 256, bagg_in, bv0, B1, mask0);
    // layer 2
    gather_kernel<<<wblocks, TB>>>(B1, AGG);
    gemm_mma<2, true, true, true><<<gblocks, 512, GEMM_SMEM>>>(AGG, B1, Whi + OFF_AGG_H, Wlo + OFF_AGG_H, 256, bagg_h, bv1, B2, mask1);
    // layer 3 (h -> d_out)
    gather_kernel<<<wblocks, TB>>>(B2, AGG);
    gemm_mma<2, true, true, true><<<gblocks, 512, GEMM_SMEM>>>(AGG, B2, Whi + OFF_AGG_H, Wlo + OFF_AGG_H, 256, bagg_h, bv1, out_h, mask2);
    // MLP head
    gemm_mma<1, true, false, false><<<gblocks, 512, GEMM_SMEM>>>(out_h, nullptr, Whi + OFF_MLP1, Wlo + OFF_MLP1, 128, bm1, nullptr, H, nullptr);
    mlp_out_kernel<<<wblocks, TB>>>(H, Wm2, bm2, out_y);
}